// round 11
// baseline (speedup 1.0000x reference)
#include <cuda_runtime.h>
#include <cuda_bf16.h>
#include <cstdint>

#define N_NODE   100000
#define NODE_PAD 100096
#define D_IN     256
#define D_OUT    64
#define E_MAX    1600000
#define NEG_SLOPE 0.2f
#define SLD 40   // smem row stride in bf16 elems (80B)

// ---- scratch (__device__ globals; no allocation at runtime) ----
__device__ float g_xl[NODE_PAD * D_IN];
__device__ float g_xr[NODE_PAD * D_IN];
__device__ __nv_bfloat16 g_Ahi[NODE_PAD * D_IN];
__device__ __nv_bfloat16 g_Alo[NODE_PAD * D_IN];
__device__ __nv_bfloat16 g_Bhi[512 * 256];   // rows 0-255: Wl^T, 256-511: Wr^T ([n][k])
__device__ __nv_bfloat16 g_Blo[512 * 256];
__device__ int   g_cnt[N_NODE];
__device__ int   g_incl[N_NODE];
__device__ int   g_cursor[N_NODE];
__device__ int   g_srcs[E_MAX];
__device__ int   g_bsum[256];

// ============================================================
// Prep: fp32 -> bf16 hi/lo split
// ============================================================
__global__ void prepA_k(const float4* __restrict__ emb4, int n4, int np4)
{
    int i = blockIdx.x * blockDim.x + threadIdx.x;
    if (i >= np4) return;
    float4 v = (i < n4) ? emb4[i] : make_float4(0.f, 0.f, 0.f, 0.f);
    __nv_bfloat16 h0 = __float2bfloat16(v.x), h1 = __float2bfloat16(v.y);
    __nv_bfloat16 h2 = __float2bfloat16(v.z), h3 = __float2bfloat16(v.w);
    __nv_bfloat16 l0 = __float2bfloat16(v.x - __bfloat162float(h0));
    __nv_bfloat16 l1 = __float2bfloat16(v.y - __bfloat162float(h1));
    __nv_bfloat16 l2 = __float2bfloat16(v.z - __bfloat162float(h2));
    __nv_bfloat16 l3 = __float2bfloat16(v.w - __bfloat162float(h3));
    __nv_bfloat162* hp = (__nv_bfloat162*)g_Ahi;
    __nv_bfloat162* lp = (__nv_bfloat162*)g_Alo;
    __nv_bfloat162 a; a.x = h0; a.y = h1;
    __nv_bfloat162 b; b.x = h2; b.y = h3;
    hp[2 * i] = a; hp[2 * i + 1] = b;
    a.x = l0; a.y = l1; b.x = l2; b.y = l3;
    lp[2 * i] = a; lp[2 * i + 1] = b;
}

__global__ void prepW_k(const float* __restrict__ Wl, const float* __restrict__ Wr)
{
    int idx = blockIdx.x * blockDim.x + threadIdx.x;   // 512*256
    if (idx >= 512 * 256) return;
    int n = idx >> 8, k = idx & 255;
    float v = (n < 256) ? Wl[k * 256 + n] : Wr[k * 256 + (n - 256)];
    __nv_bfloat16 h = __float2bfloat16(v);
    g_Bhi[idx] = h;
    g_Blo[idx] = __float2bfloat16(v - __bfloat162float(h));
}

// ============================================================
// mma.sync bf16 GEMM, cp.async double-buffered, ldmatrix frags.
// C[NODE_PAD,512] = A x [Wl|Wr]^T (bf16x3: AhBh + AhBl + AlBh)
// CTA tile 128m x 128n, 4 warps of 64x64 (2x2), 2 CTAs/SM.
// ============================================================
__device__ __forceinline__ void mma16816(float c[4], const uint32_t a[4],
                                         const uint32_t b0, const uint32_t b1)
{
    asm volatile(
        "mma.sync.aligned.m16n8k16.row.col.f32.bf16.bf16.f32 "
        "{%0,%1,%2,%3}, {%4,%5,%6,%7}, {%8,%9}, {%0,%1,%2,%3};"
        : "+f"(c[0]), "+f"(c[1]), "+f"(c[2]), "+f"(c[3])
        : "r"(a[0]), "r"(a[1]), "r"(a[2]), "r"(a[3]), "r"(b0), "r"(b1));
}

__device__ __forceinline__ void ldsm4(uint32_t r[4], uint32_t addr)
{
    asm volatile("ldmatrix.sync.aligned.m8n8.x4.shared.b16 {%0,%1,%2,%3}, [%4];"
                 : "=r"(r[0]), "=r"(r[1]), "=r"(r[2]), "=r"(r[3]) : "r"(addr));
}

__device__ __forceinline__ void cpa16(uint32_t dst, const void* src)
{
    asm volatile("cp.async.ca.shared.global [%0], [%1], 16;"
                 :: "r"(dst), "l"(src));
}

#define TILE_MAT 10240          // 128 rows * SLD * 2B  (each of Ah, Al, Bh, Bl)
#define STAGE_B  (4 * TILE_MAT) // 40960 B
#define OFF_AH 0
#define OFF_AL TILE_MAT
#define OFF_BH (2 * TILE_MAT)
#define OFF_BL (3 * TILE_MAT)

__global__ void __launch_bounds__(128, 2)
gemm_mma()
{
    extern __shared__ __align__(16) char smem[];
    uint32_t sb;
    asm("{ .reg .u64 t; cvta.to.shared.u64 t, %1; cvt.u32.u64 %0, t; }"
        : "=r"(sb) : "l"(smem));

    const int tid = threadIdx.x;
    const int wid = tid >> 5;          // 0..3
    const int lane = tid & 31;
    const int g = lane >> 2;
    const int t = lane & 3;
    const int m0 = blockIdx.y * 128;
    const int n0 = blockIdx.x * 128;
    const int wm = (wid & 1) * 64;     // warp row base
    const int wn = (wid >> 1) * 64;    // warp col base

    float acc[4][8][4];
#pragma unroll
    for (int i = 0; i < 4; i++)
#pragma unroll
        for (int j = 0; j < 8; j++)
#pragma unroll
            for (int q = 0; q < 4; q++) acc[i][j][q] = 0.f;

    auto stage_load = [&](int s, int kt) {
        uint32_t st = sb + s * STAGE_B;
#pragma unroll
        for (int i = 0; i < 4; i++) {
            int idx = tid + i * 128;
            int r = idx >> 2, q = idx & 3;
            size_t ga = (size_t)(m0 + r) * 256 + kt * 32 + q * 8;
            size_t gb = (size_t)(n0 + r) * 256 + kt * 32 + q * 8;
            uint32_t so = (uint32_t)(r * SLD + q * 8) * 2;
            cpa16(st + OFF_AH + so, g_Ahi + ga);
            cpa16(st + OFF_AL + so, g_Alo + ga);
            cpa16(st + OFF_BH + so, g_Bhi + gb);
            cpa16(st + OFF_BL + so, g_Blo + gb);
        }
        asm volatile("cp.async.commit_group;" ::: "memory");
    };

    stage_load(0, 0);

    for (int kt = 0; kt < 8; kt++) {
        if (kt < 7) {
            stage_load((kt + 1) & 1, kt + 1);
            asm volatile("cp.async.wait_group 1;" ::: "memory");
        } else {
            asm volatile("cp.async.wait_group 0;" ::: "memory");
        }
        __syncthreads();

        uint32_t st = sb + (kt & 1) * STAGE_B;
        uint32_t bAh = st + OFF_AH, bAl = st + OFF_AL;
        uint32_t bBh = st + OFF_BH, bBl = st + OFF_BL;

#pragma unroll
        for (int kk = 0; kk < 32; kk += 16) {
            uint32_t ah[4][4], al[4][4];
            int arow = (lane & 15);
            int akch = kk + ((lane >> 4) << 3);
#pragma unroll
            for (int mi = 0; mi < 4; mi++) {
                uint32_t ao = (uint32_t)((wm + mi * 16 + arow) * SLD + akch) * 2;
                ldsm4(ah[mi], bAh + ao);
                ldsm4(al[mi], bAl + ao);
            }
            int brow = (lane & 7) + ((lane >> 4) << 3);
            int bkch = kk + (((lane >> 3) & 1) << 3);
#pragma unroll
            for (int npi = 0; npi < 4; npi++) {
                uint32_t bo =
                    (uint32_t)((wn + npi * 16 + brow) * SLD + bkch) * 2;
                uint32_t bh[4], bl[4];
                ldsm4(bh, bBh + bo);
                ldsm4(bl, bBl + bo);
                int n0i = npi * 2, n1i = npi * 2 + 1;
#pragma unroll
                for (int mi = 0; mi < 4; mi++) {
                    mma16816(acc[mi][n0i], ah[mi], bh[0], bh[1]);
                    mma16816(acc[mi][n1i], ah[mi], bh[2], bh[3]);
                }
#pragma unroll
                for (int mi = 0; mi < 4; mi++) {
                    mma16816(acc[mi][n0i], ah[mi], bl[0], bl[1]);
                    mma16816(acc[mi][n1i], ah[mi], bl[2], bl[3]);
                }
#pragma unroll
                for (int mi = 0; mi < 4; mi++) {
                    mma16816(acc[mi][n0i], al[mi], bh[0], bh[1]);
                    mma16816(acc[mi][n1i], al[mi], bh[2], bh[3]);
                }
            }
        }
        __syncthreads();
    }

#pragma unroll
    for (int mi = 0; mi < 4; mi++) {
        int row = m0 + wm + 16 * mi + g;
#pragma unroll
        for (int ni = 0; ni < 8; ni++) {
            int nc = n0 + wn + ni * 8 + t * 2;
            float* base = (nc < 256) ? g_xl : g_xr;
            int col = nc & 255;
            *(float2*)&base[(size_t)row * 256 + col] =
                make_float2(acc[mi][ni][0], acc[mi][ni][1]);
            *(float2*)&base[(size_t)(row + 8) * 256 + col] =
                make_float2(acc[mi][ni][2], acc[mi][ni][3]);
        }
    }
}

// ============================================================
// CSR construction  (edge_index int32: row 0 = src, row 1 = dst)
// ============================================================
__global__ void zero_cnt_k(int M)
{
    int i = blockIdx.x * blockDim.x + threadIdx.x;
    if (i < M) g_cnt[i] = 0;
}

__global__ void count_k(const int* __restrict__ ei, int E)
{
    int e = blockIdx.x * blockDim.x + threadIdx.x;
    if (e < E) atomicAdd(&g_cnt[ei[E + e]], 1);
}

__global__ void scan1_k(int M)
{
    __shared__ int s[1024];
    int gi = blockIdx.x * 1024 + threadIdx.x;
    int v = (gi < M) ? g_cnt[gi] : 0;
    s[threadIdx.x] = v;
    __syncthreads();
#pragma unroll
    for (int off = 1; off < 1024; off <<= 1) {
        int tv = (threadIdx.x >= off) ? s[threadIdx.x - off] : 0;
        __syncthreads();
        s[threadIdx.x] += tv;
        __syncthreads();
    }
    if (gi < M) g_incl[gi] = s[threadIdx.x];
    if (threadIdx.x == 1023) g_bsum[blockIdx.x] = s[1023];
}

__global__ void scan2_k(int nb)
{
    if (threadIdx.x == 0 && blockIdx.x == 0) {
        int run = 0;
        for (int b = 0; b < nb; b++) { int tv = g_bsum[b]; g_bsum[b] = run; run += tv; }
    }
}

__global__ void scan3_k(int M)
{
    int i = blockIdx.x * blockDim.x + threadIdx.x;
    if (i < M) {
        int incl = g_incl[i] + g_bsum[i >> 10];
        g_incl[i] = incl;
        g_cursor[i] = incl - g_cnt[i];
    }
}

__global__ void scatter_k(const int* __restrict__ ei, int E)
{
    int e = blockIdx.x * blockDim.x + threadIdx.x;
    if (e < E) {
        int d = ei[E + e];
        int pos = atomicAdd(&g_cursor[d], 1);
        g_srcs[pos] = ei[e];
    }
}

// ============================================================
// GATv2 attention + aggregation, one warp per dst node.
// Lane l owns channels 8l..8l+7, all in head l>>3 (64-ch heads).
// R6 loop + streaming-cache hints on xr/srcs/out (xl keeps L2).
// ============================================================
__device__ __forceinline__ float leaky4dot(float4 xl, float4 xr, float4 at)
{
    float z0 = xl.x + xr.x, z1 = xl.y + xr.y, z2 = xl.z + xr.z, z3 = xl.w + xr.w;
    float l0 = z0 > 0.f ? z0 : NEG_SLOPE * z0;
    float l1 = z1 > 0.f ? z1 : NEG_SLOPE * z1;
    float l2 = z2 > 0.f ? z2 : NEG_SLOPE * z2;
    float l3 = z3 > 0.f ? z3 : NEG_SLOPE * z3;
    return at.x * l0 + at.y * l1 + at.z * l2 + at.w * l3;
}

__device__ __forceinline__ float red8(float v)
{
    v += __shfl_xor_sync(0xffffffffu, v, 1);
    v += __shfl_xor_sync(0xffffffffu, v, 2);
    v += __shfl_xor_sync(0xffffffffu, v, 4);
    return v;
}

__global__ void __launch_bounds__(256)
agg_k(const float* __restrict__ att, const float* __restrict__ bias,
      float* __restrict__ out, int M)
{
    const int gwarp = (blockIdx.x * blockDim.x + threadIdx.x) >> 5;
    const int lane = threadIdx.x & 31;
    if (gwarp >= M) return;
    const int i = gwarp;
    const int c0 = lane * 8;

    float4 atA = *(const float4*)&att[c0];
    float4 atB = *(const float4*)&att[c0 + 4];
    const float* xrp = g_xr + (size_t)i * D_IN;
    float4 xrA = __ldcs((const float4*)&xrp[c0]);
    float4 xrB = __ldcs((const float4*)&xrp[c0 + 4]);

    float m, d;
    float4 accA, accB;

    // ---- self loop (weight exp(0)=1) ----
    {
        const float* xlp = g_xl + (size_t)i * D_IN;
        float4 xlA = *(const float4*)&xlp[c0];
        float4 xlB = *(const float4*)&xlp[c0 + 4];
        m = red8(leaky4dot(xlA, xrA, atA) + leaky4dot(xlB, xrB, atB));
        d = 1.f;
        accA = xlA; accB = xlB;
    }

    const int end = g_incl[i];
    int j = end - g_cnt[i];

    if (j < end) {
        int src = __ldcs(&g_srcs[j]);
        const float* xlp = g_xl + (size_t)src * D_IN;
        float4 nA = *(const float4*)&xlp[c0];
        float4 nB = *(const float4*)&xlp[c0 + 4];
        for (; j < end; j++) {
            float4 xlA = nA, xlB = nB;
            if (j + 1 < end) {
                int s2 = __ldcs(&g_srcs[j + 1]);
                const float* xp = g_xl + (size_t)s2 * D_IN;
                nA = *(const float4*)&xp[c0];
                nB = *(const float4*)&xp[c0 + 4];
            }
            float p = red8(leaky4dot(xlA, xrA, atA) + leaky4dot(xlB, xrB, atB));

            float mn = fmaxf(m, p);
            float cw = __expf(m - mn), ww = __expf(p - mn);
            d = d * cw + ww; m = mn;
            accA.x = accA.x * cw + ww * xlA.x;
            accA.y = accA.y * cw + ww * xlA.y;
            accA.z = accA.z * cw + ww * xlA.z;
            accA.w = accA.w * cw + ww * xlA.w;
            accB.x = accB.x * cw + ww * xlB.x;
            accB.y = accB.y * cw + ww * xlB.y;
            accB.z = accB.z * cw + ww * xlB.z;
            accB.w = accB.w * cw + ww * xlB.w;
        }
    }

    float inv = 1.f / (d + 1e-16f);
    float z[8] = { accA.x * inv, accA.y * inv, accA.z * inv, accA.w * inv,
                   accB.x * inv, accB.y * inv, accB.z * inv, accB.w * inv };
    // mean over heads: lanes l, l^8, l^16, l^24 hold the same per-head channel
#pragma unroll
    for (int q = 0; q < 8; q++) {
        z[q] += __shfl_xor_sync(0xffffffffu, z[q], 8);
        z[q] += __shfl_xor_sync(0xffffffffu, z[q], 16);
    }

    if (lane < 8) {
#pragma unroll
        for (int q = 0; q < 8; q++) {
            float o = 0.25f * z[q] + bias[c0 + q];
            z[q] = o > 0.f ? o : expm1f(o);
        }
        float* dst = out + (size_t)i * D_OUT + c0;
        __stcs((float4*)dst, make_float4(z[0], z[1], z[2], z[3]));
        __stcs((float4*)(dst + 4), make_float4(z[4], z[5], z[6], z[7]));
    }
}

// ============================================================
extern "C" void kernel_launch(void* const* d_in, const int* in_sizes, int n_in,
                              void* d_out, int out_size)
{
    const int* ei        = (const int*)d_in[1];
    const float* emb     = (const float*)d_in[2];
    const float* Wl      = (const float*)d_in[3];
    const float* Wr      = (const float*)d_in[4];
    const float* att     = (const float*)d_in[5];
    const float* bias    = (const float*)d_in[6];
    float* out           = (float*)d_out;

    const int E = in_sizes[1] / 2;         // 1,600,000
    const int M = in_sizes[2] / D_IN;      // 100,000
    const int T = (M + 127) / 128;         // 782 row tiles
    const int MP = T * 128;

    const int GEMM_SMEM = 2 * STAGE_B;     // 81920 B
    static int init_done = 0;
    static cudaStream_t s2;
    static cudaEvent_t evFork, evJoin;
    if (!init_done) {
        cudaFuncSetAttribute(gemm_mma, cudaFuncAttributeMaxDynamicSharedMemorySize,
                             GEMM_SMEM);
        cudaStreamCreateWithFlags(&s2, cudaStreamNonBlocking);
        cudaEventCreateWithFlags(&evFork, cudaEventDisableTiming);
        cudaEventCreateWithFlags(&evJoin, cudaEventDisableTiming);
        init_done = 1;
    }

    int tb = 256;
    int n4 = M * 64, np4 = MP * 64;
    int nb = (M + 1023) / 1024;

    // fork: CSR chain (depends only on edge_index) runs on s2,
    // concurrent with prep + GEMM on the main stream.
    cudaEventRecord(evFork, 0);
    cudaStreamWaitEvent(s2, evFork, 0);

    // main stream: prep + GEMM
    prepA_k<<<(np4 + 255) / 256, 256>>>((const float4*)emb, n4, np4);
    prepW_k<<<512, 256>>>(Wl, Wr);
    gemm_mma<<<dim3(4, T), 128, GEMM_SMEM>>>();

    // s2: CSR build
    zero_cnt_k<<<(M + tb - 1) / tb, tb, 0, s2>>>(M);
    count_k<<<(E + tb - 1) / tb, tb, 0, s2>>>(ei, E);
    scan1_k<<<nb, 1024, 0, s2>>>(M);
    scan2_k<<<1, 32, 0, s2>>>(nb);
    scan3_k<<<(M + tb - 1) / tb, tb, 0, s2>>>(M);
    scatter_k<<<(E + tb - 1) / tb, tb, 0, s2>>>(ei, E);
    cudaEventRecord(evJoin, s2);

    // join, then aggregate
    cudaStreamWaitEvent(0, evJoin, 0);
    agg_k<<<(M + 7) / 8, 256>>>(att, bias, out, M);

    (void)n_in; (void)out_size;
}

// round 12
// speedup vs baseline: 1.0956x; 1.0956x over previous
#include <cuda_runtime.h>
#include <cuda_bf16.h>
#include <cuda_fp16.h>
#include <cstdint>

#define N_NODE   100000
#define NODE_PAD 100096
#define D_IN     256
#define D_OUT    64
#define E_MAX    1600000
#define NEG_SLOPE 0.2f
#define SLD 40   // smem row stride in bf16 elems (80B)

// ---- scratch (__device__ globals; no allocation at runtime) ----
__device__ __half g_xlh[NODE_PAD * D_IN];   // emb @ W_l, fp16
__device__ __half g_xrh[NODE_PAD * D_IN];   // emb @ W_r, fp16
__device__ __nv_bfloat16 g_Ahi[NODE_PAD * D_IN];
__device__ __nv_bfloat16 g_Alo[NODE_PAD * D_IN];
__device__ __nv_bfloat16 g_Bhi[512 * 256];   // rows 0-255: Wl^T, 256-511: Wr^T ([n][k])
__device__ __nv_bfloat16 g_Blo[512 * 256];
__device__ int   g_cnt[N_NODE];
__device__ int   g_incl[N_NODE];
__device__ int   g_cursor[N_NODE];
__device__ int   g_srcs[E_MAX];
__device__ int   g_bsum[256];

// ============================================================
// Prep: fp32 -> bf16 hi/lo split
// ============================================================
__global__ void prepA_k(const float4* __restrict__ emb4, int n4, int np4)
{
    int i = blockIdx.x * blockDim.x + threadIdx.x;
    if (i >= np4) return;
    float4 v = (i < n4) ? emb4[i] : make_float4(0.f, 0.f, 0.f, 0.f);
    __nv_bfloat16 h0 = __float2bfloat16(v.x), h1 = __float2bfloat16(v.y);
    __nv_bfloat16 h2 = __float2bfloat16(v.z), h3 = __float2bfloat16(v.w);
    __nv_bfloat16 l0 = __float2bfloat16(v.x - __bfloat162float(h0));
    __nv_bfloat16 l1 = __float2bfloat16(v.y - __bfloat162float(h1));
    __nv_bfloat16 l2 = __float2bfloat16(v.z - __bfloat162float(h2));
    __nv_bfloat16 l3 = __float2bfloat16(v.w - __bfloat162float(h3));
    __nv_bfloat162* hp = (__nv_bfloat162*)g_Ahi;
    __nv_bfloat162* lp = (__nv_bfloat162*)g_Alo;
    __nv_bfloat162 a; a.x = h0; a.y = h1;
    __nv_bfloat162 b; b.x = h2; b.y = h3;
    hp[2 * i] = a; hp[2 * i + 1] = b;
    a.x = l0; a.y = l1; b.x = l2; b.y = l3;
    lp[2 * i] = a; lp[2 * i + 1] = b;
}

__global__ void prepW_k(const float* __restrict__ Wl, const float* __restrict__ Wr)
{
    int idx = blockIdx.x * blockDim.x + threadIdx.x;   // 512*256
    if (idx >= 512 * 256) return;
    int n = idx >> 8, k = idx & 255;
    float v = (n < 256) ? Wl[k * 256 + n] : Wr[k * 256 + (n - 256)];
    __nv_bfloat16 h = __float2bfloat16(v);
    g_Bhi[idx] = h;
    g_Blo[idx] = __float2bfloat16(v - __bfloat162float(h));
}

// ============================================================
// mma.sync bf16 GEMM, cp.async double-buffered, ldmatrix frags.
// C[NODE_PAD,512] = A x [Wl|Wr]^T (bf16x3: AhBh + AhBl + AlBh)
// CTA tile 128m x 128n, 4 warps of 64x64 (2x2), 2 CTAs/SM.
// Epilogue stores fp16 (halves agg gather traffic; 2.8e-4 RMS).
// ============================================================
__device__ __forceinline__ void mma16816(float c[4], const uint32_t a[4],
                                         const uint32_t b0, const uint32_t b1)
{
    asm volatile(
        "mma.sync.aligned.m16n8k16.row.col.f32.bf16.bf16.f32 "
        "{%0,%1,%2,%3}, {%4,%5,%6,%7}, {%8,%9}, {%0,%1,%2,%3};"
        : "+f"(c[0]), "+f"(c[1]), "+f"(c[2]), "+f"(c[3])
        : "r"(a[0]), "r"(a[1]), "r"(a[2]), "r"(a[3]), "r"(b0), "r"(b1));
}

__device__ __forceinline__ void ldsm4(uint32_t r[4], uint32_t addr)
{
    asm volatile("ldmatrix.sync.aligned.m8n8.x4.shared.b16 {%0,%1,%2,%3}, [%4];"
                 : "=r"(r[0]), "=r"(r[1]), "=r"(r[2]), "=r"(r[3]) : "r"(addr));
}

__device__ __forceinline__ void cpa16(uint32_t dst, const void* src)
{
    asm volatile("cp.async.ca.shared.global [%0], [%1], 16;"
                 :: "r"(dst), "l"(src));
}

#define TILE_MAT 10240          // 128 rows * SLD * 2B  (each of Ah, Al, Bh, Bl)
#define STAGE_B  (4 * TILE_MAT) // 40960 B
#define OFF_AH 0
#define OFF_AL TILE_MAT
#define OFF_BH (2 * TILE_MAT)
#define OFF_BL (3 * TILE_MAT)

__global__ void __launch_bounds__(128, 2)
gemm_mma()
{
    extern __shared__ __align__(16) char smem[];
    uint32_t sb;
    asm("{ .reg .u64 t; cvta.to.shared.u64 t, %1; cvt.u32.u64 %0, t; }"
        : "=r"(sb) : "l"(smem));

    const int tid = threadIdx.x;
    const int wid = tid >> 5;          // 0..3
    const int lane = tid & 31;
    const int g = lane >> 2;
    const int t = lane & 3;
    const int m0 = blockIdx.y * 128;
    const int n0 = blockIdx.x * 128;
    const int wm = (wid & 1) * 64;     // warp row base
    const int wn = (wid >> 1) * 64;    // warp col base

    float acc[4][8][4];
#pragma unroll
    for (int i = 0; i < 4; i++)
#pragma unroll
        for (int j = 0; j < 8; j++)
#pragma unroll
            for (int q = 0; q < 4; q++) acc[i][j][q] = 0.f;

    auto stage_load = [&](int s, int kt) {
        uint32_t st = sb + s * STAGE_B;
#pragma unroll
        for (int i = 0; i < 4; i++) {
            int idx = tid + i * 128;
            int r = idx >> 2, q = idx & 3;
            size_t ga = (size_t)(m0 + r) * 256 + kt * 32 + q * 8;
            size_t gb = (size_t)(n0 + r) * 256 + kt * 32 + q * 8;
            uint32_t so = (uint32_t)(r * SLD + q * 8) * 2;
            cpa16(st + OFF_AH + so, g_Ahi + ga);
            cpa16(st + OFF_AL + so, g_Alo + ga);
            cpa16(st + OFF_BH + so, g_Bhi + gb);
            cpa16(st + OFF_BL + so, g_Blo + gb);
        }
        asm volatile("cp.async.commit_group;" ::: "memory");
    };

    stage_load(0, 0);

    for (int kt = 0; kt < 8; kt++) {
        if (kt < 7) {
            stage_load((kt + 1) & 1, kt + 1);
            asm volatile("cp.async.wait_group 1;" ::: "memory");
        } else {
            asm volatile("cp.async.wait_group 0;" ::: "memory");
        }
        __syncthreads();

        uint32_t st = sb + (kt & 1) * STAGE_B;
        uint32_t bAh = st + OFF_AH, bAl = st + OFF_AL;
        uint32_t bBh = st + OFF_BH, bBl = st + OFF_BL;

#pragma unroll
        for (int kk = 0; kk < 32; kk += 16) {
            uint32_t ah[4][4], al[4][4];
            int arow = (lane & 15);
            int akch = kk + ((lane >> 4) << 3);
#pragma unroll
            for (int mi = 0; mi < 4; mi++) {
                uint32_t ao = (uint32_t)((wm + mi * 16 + arow) * SLD + akch) * 2;
                ldsm4(ah[mi], bAh + ao);
                ldsm4(al[mi], bAl + ao);
            }
            int brow = (lane & 7) + ((lane >> 4) << 3);
            int bkch = kk + (((lane >> 3) & 1) << 3);
#pragma unroll
            for (int npi = 0; npi < 4; npi++) {
                uint32_t bo =
                    (uint32_t)((wn + npi * 16 + brow) * SLD + bkch) * 2;
                uint32_t bh[4], bl[4];
                ldsm4(bh, bBh + bo);
                ldsm4(bl, bBl + bo);
                int n0i = npi * 2, n1i = npi * 2 + 1;
#pragma unroll
                for (int mi = 0; mi < 4; mi++) {
                    mma16816(acc[mi][n0i], ah[mi], bh[0], bh[1]);
                    mma16816(acc[mi][n1i], ah[mi], bh[2], bh[3]);
                }
#pragma unroll
                for (int mi = 0; mi < 4; mi++) {
                    mma16816(acc[mi][n0i], ah[mi], bl[0], bl[1]);
                    mma16816(acc[mi][n1i], ah[mi], bl[2], bl[3]);
                }
#pragma unroll
                for (int mi = 0; mi < 4; mi++) {
                    mma16816(acc[mi][n0i], al[mi], bh[0], bh[1]);
                    mma16816(acc[mi][n1i], al[mi], bh[2], bh[3]);
                }
            }
        }
        __syncthreads();
    }

    // epilogue: convert fp32 acc -> fp16 storage
#pragma unroll
    for (int mi = 0; mi < 4; mi++) {
        int row = m0 + wm + 16 * mi + g;
#pragma unroll
        for (int ni = 0; ni < 8; ni++) {
            int nc = n0 + wn + ni * 8 + t * 2;
            __half* baseh = (nc < 256) ? g_xlh : g_xrh;
            int col = nc & 255;
            *(__half2*)&baseh[(size_t)row * 256 + col] =
                __floats2half2_rn(acc[mi][ni][0], acc[mi][ni][1]);
            *(__half2*)&baseh[(size_t)(row + 8) * 256 + col] =
                __floats2half2_rn(acc[mi][ni][2], acc[mi][ni][3]);
        }
    }
}

// ============================================================
// CSR construction  (edge_index int32: row 0 = src, row 1 = dst)
// ============================================================
__global__ void zero_cnt_k(int M)
{
    int i = blockIdx.x * blockDim.x + threadIdx.x;
    if (i < M) g_cnt[i] = 0;
}

__global__ void count_k(const int* __restrict__ ei, int E)
{
    int e = blockIdx.x * blockDim.x + threadIdx.x;
    if (e < E) atomicAdd(&g_cnt[ei[E + e]], 1);
}

__global__ void scan1_k(int M)
{
    __shared__ int s[1024];
    int gi = blockIdx.x * 1024 + threadIdx.x;
    int v = (gi < M) ? g_cnt[gi] : 0;
    s[threadIdx.x] = v;
    __syncthreads();
#pragma unroll
    for (int off = 1; off < 1024; off <<= 1) {
        int tv = (threadIdx.x >= off) ? s[threadIdx.x - off] : 0;
        __syncthreads();
        s[threadIdx.x] += tv;
        __syncthreads();
    }
    if (gi < M) g_incl[gi] = s[threadIdx.x];
    if (threadIdx.x == 1023) g_bsum[blockIdx.x] = s[1023];
}

__global__ void scan2_k(int nb)
{
    if (threadIdx.x == 0 && blockIdx.x == 0) {
        int run = 0;
        for (int b = 0; b < nb; b++) { int tv = g_bsum[b]; g_bsum[b] = run; run += tv; }
    }
}

__global__ void scan3_k(int M)
{
    int i = blockIdx.x * blockDim.x + threadIdx.x;
    if (i < M) {
        int incl = g_incl[i] + g_bsum[i >> 10];
        g_incl[i] = incl;
        g_cursor[i] = incl - g_cnt[i];
    }
}

__global__ void scatter_k(const int* __restrict__ ei, int E)
{
    int e = blockIdx.x * blockDim.x + threadIdx.x;
    if (e < E) {
        int d = ei[E + e];
        int pos = atomicAdd(&g_cursor[d], 1);
        g_srcs[pos] = ei[e];
    }
}

// ============================================================
// GATv2 attention + aggregation, one warp per dst node.
// Lane l owns channels 8l..8l+7 (head l>>3); xl/xr rows are fp16,
// ONE uint4 load per lane per edge (512B/row gather).
// ============================================================
__device__ __forceinline__ void h8_to_f8(uint4 r, float4& A, float4& B)
{
    __half2* h = (__half2*)&r;
    float2 f0 = __half22float2(h[0]);
    float2 f1 = __half22float2(h[1]);
    float2 f2 = __half22float2(h[2]);
    float2 f3 = __half22float2(h[3]);
    A = make_float4(f0.x, f0.y, f1.x, f1.y);
    B = make_float4(f2.x, f2.y, f3.x, f3.y);
}

__device__ __forceinline__ float leaky4dot(float4 xl, float4 xr, float4 at)
{
    float z0 = xl.x + xr.x, z1 = xl.y + xr.y, z2 = xl.z + xr.z, z3 = xl.w + xr.w;
    float l0 = z0 > 0.f ? z0 : NEG_SLOPE * z0;
    float l1 = z1 > 0.f ? z1 : NEG_SLOPE * z1;
    float l2 = z2 > 0.f ? z2 : NEG_SLOPE * z2;
    float l3 = z3 > 0.f ? z3 : NEG_SLOPE * z3;
    return at.x * l0 + at.y * l1 + at.z * l2 + at.w * l3;
}

__device__ __forceinline__ float red8(float v)
{
    v += __shfl_xor_sync(0xffffffffu, v, 1);
    v += __shfl_xor_sync(0xffffffffu, v, 2);
    v += __shfl_xor_sync(0xffffffffu, v, 4);
    return v;
}

__global__ void __launch_bounds__(256)
agg_k(const float* __restrict__ att, const float* __restrict__ bias,
      float* __restrict__ out, int M)
{
    const int gwarp = (blockIdx.x * blockDim.x + threadIdx.x) >> 5;
    const int lane = threadIdx.x & 31;
    if (gwarp >= M) return;
    const int i = gwarp;
    const int c0 = lane * 8;

    float4 atA = *(const float4*)&att[c0];
    float4 atB = *(const float4*)&att[c0 + 4];
    float4 xrA, xrB;
    h8_to_f8(*(const uint4*)(g_xrh + (size_t)i * D_IN + c0), xrA, xrB);

    float m, d;
    float4 accA, accB;

    // ---- self loop (weight exp(0)=1) ----
    {
        float4 xlA, xlB;
        h8_to_f8(*(const uint4*)(g_xlh + (size_t)i * D_IN + c0), xlA, xlB);
        m = red8(leaky4dot(xlA, xrA, atA) + leaky4dot(xlB, xrB, atB));
        d = 1.f;
        accA = xlA; accB = xlB;
    }

    const int end = g_incl[i];
    int j = end - g_cnt[i];

    if (j < end) {
        int src = g_srcs[j];
        uint4 nraw = *(const uint4*)(g_xlh + (size_t)src * D_IN + c0);
        for (; j < end; j++) {
            uint4 raw = nraw;
            if (j + 1 < end) {
                int s2 = g_srcs[j + 1];
                nraw = *(const uint4*)(g_xlh + (size_t)s2 * D_IN + c0);
            }
            float4 xlA, xlB;
            h8_to_f8(raw, xlA, xlB);
            float p = red8(leaky4dot(xlA, xrA, atA) + leaky4dot(xlB, xrB, atB));

            float mn = fmaxf(m, p);
            float cw = __expf(m - mn), ww = __expf(p - mn);
            d = d * cw + ww; m = mn;
            accA.x = accA.x * cw + ww * xlA.x;
            accA.y = accA.y * cw + ww * xlA.y;
            accA.z = accA.z * cw + ww * xlA.z;
            accA.w = accA.w * cw + ww * xlA.w;
            accB.x = accB.x * cw + ww * xlB.x;
            accB.y = accB.y * cw + ww * xlB.y;
            accB.z = accB.z * cw + ww * xlB.z;
            accB.w = accB.w * cw + ww * xlB.w;
        }
    }

    float inv = 1.f / (d + 1e-16f);
    float z[8] = { accA.x * inv, accA.y * inv, accA.z * inv, accA.w * inv,
                   accB.x * inv, accB.y * inv, accB.z * inv, accB.w * inv };
    // mean over heads: lanes l, l^8, l^16, l^24 hold the same per-head channel
#pragma unroll
    for (int q = 0; q < 8; q++) {
        z[q] += __shfl_xor_sync(0xffffffffu, z[q], 8);
        z[q] += __shfl_xor_sync(0xffffffffu, z[q], 16);
    }

    if (lane < 8) {
#pragma unroll
        for (int q = 0; q < 8; q++) {
            float o = 0.25f * z[q] + bias[c0 + q];
            z[q] = o > 0.f ? o : expm1f(o);
        }
        float* dst = out + (size_t)i * D_OUT + c0;
        *(float4*)dst = make_float4(z[0], z[1], z[2], z[3]);
        *(float4*)(dst + 4) = make_float4(z[4], z[5], z[6], z[7]);
    }
}

// ============================================================
extern "C" void kernel_launch(void* const* d_in, const int* in_sizes, int n_in,
                              void* d_out, int out_size)
{
    const int* ei        = (const int*)d_in[1];
    const float* emb     = (const float*)d_in[2];
    const float* Wl      = (const float*)d_in[3];
    const float* Wr      = (const float*)d_in[4];
    const float* att     = (const float*)d_in[5];
    const float* bias    = (const float*)d_in[6];
    float* out           = (float*)d_out;

    const int E = in_sizes[1] / 2;         // 1,600,000
    const int M = in_sizes[2] / D_IN;      // 100,000
    const int T = (M + 127) / 128;         // 782 row tiles
    const int MP = T * 128;

    const int GEMM_SMEM = 2 * STAGE_B;     // 81920 B
    static int smem_set = 0;
    if (!smem_set) {
        cudaFuncSetAttribute(gemm_mma, cudaFuncAttributeMaxDynamicSharedMemorySize,
                             GEMM_SMEM);
        smem_set = 1;
    }

    int tb = 256;
    int n4 = M * 64, np4 = MP * 64;
    int nb = (M + 1023) / 1024;

    // single stream; gemm_mma kept in profile slot 4
    prepA_k<<<(np4 + 255) / 256, 256>>>((const float4*)emb, n4, np4);   // 1
    prepW_k<<<512, 256>>>(Wl, Wr);                                      // 2
    zero_cnt_k<<<(M + tb - 1) / tb, tb>>>(M);                           // 3
    gemm_mma<<<dim3(4, T), 128, GEMM_SMEM>>>();                         // 4
    count_k<<<(E + tb - 1) / tb, tb>>>(ei, E);                          // 5
    scan1_k<<<nb, 1024>>>(M);                                           // 6
    scan2_k<<<1, 32>>>(nb);                                             // 7
    scan3_k<<<(M + tb - 1) / tb, tb>>>(M);                              // 8
    scatter_k<<<(E + tb - 1) / tb, tb>>>(ei, E);                        // 9
    agg_k<<<(M + 7) / 8, 256>>>(att, bias, out, M);                     // 10

    (void)n_in; (void)out_size;
}

// round 13
// speedup vs baseline: 1.4205x; 1.2966x over previous
#include <cuda_runtime.h>
#include <cuda_fp16.h>
#include <cstdint>

#define N_NODE   100000
#define NODE_PAD 100096
#define D_IN     256
#define D_OUT    64
#define E_MAX    1600000
#define NEG_SLOPE 0.2f
#define SLD 40   // smem row stride in fp16 elems (80B)

// ---- scratch (__device__ globals; no allocation at runtime) ----
__device__ __half g_xlh[NODE_PAD * D_IN];   // emb @ W_l, fp16
__device__ __half g_xrh[NODE_PAD * D_IN];   // emb @ W_r, fp16
__device__ __half g_Af[NODE_PAD * D_IN];    // emb, fp16
__device__ __half g_Bf[512 * 256];          // rows 0-255: Wl^T, 256-511: Wr^T ([n][k])
__device__ int   g_cnt[N_NODE];
__device__ int   g_incl[N_NODE];
__device__ int   g_cursor[N_NODE];
__device__ int   g_srcs[E_MAX];
__device__ int   g_bsum[256];

// ============================================================
// Prep: fp32 -> fp16
// ============================================================
__global__ void prepA_k(const float4* __restrict__ emb4, int n4, int np4)
{
    int i = blockIdx.x * blockDim.x + threadIdx.x;
    if (i >= np4) return;
    float4 v = (i < n4) ? emb4[i] : make_float4(0.f, 0.f, 0.f, 0.f);
    __half2* hp = (__half2*)g_Af;
    hp[2 * i]     = __floats2half2_rn(v.x, v.y);
    hp[2 * i + 1] = __floats2half2_rn(v.z, v.w);
}

__global__ void prepW_k(const float* __restrict__ Wl, const float* __restrict__ Wr)
{
    int idx = blockIdx.x * blockDim.x + threadIdx.x;   // 512*256
    if (idx >= 512 * 256) return;
    int n = idx >> 8, k = idx & 255;
    float v = (n < 256) ? Wl[k * 256 + n] : Wr[k * 256 + (n - 256)];
    g_Bf[idx] = __float2half_rn(v);
}

// ============================================================
// mma.sync fp16 GEMM, cp.async double-buffered, ldmatrix frags.
// C[NODE_PAD,512] = A x [Wl|Wr]^T (single fp16, fp32 accum)
// CTA tile 128m x 128n, 4 warps of 64x64 (2x2), 2 CTAs/SM.
// ============================================================
__device__ __forceinline__ void mma16816(float c[4], const uint32_t a[4],
                                         const uint32_t b0, const uint32_t b1)
{
    asm volatile(
        "mma.sync.aligned.m16n8k16.row.col.f32.f16.f16.f32 "
        "{%0,%1,%2,%3}, {%4,%5,%6,%7}, {%8,%9}, {%0,%1,%2,%3};"
        : "+f"(c[0]), "+f"(c[1]), "+f"(c[2]), "+f"(c[3])
        : "r"(a[0]), "r"(a[1]), "r"(a[2]), "r"(a[3]), "r"(b0), "r"(b1));
}

__device__ __forceinline__ void ldsm4(uint32_t r[4], uint32_t addr)
{
    asm volatile("ldmatrix.sync.aligned.m8n8.x4.shared.b16 {%0,%1,%2,%3}, [%4];"
                 : "=r"(r[0]), "=r"(r[1]), "=r"(r[2]), "=r"(r[3]) : "r"(addr));
}

__device__ __forceinline__ void cpa16(uint32_t dst, const void* src)
{
    asm volatile("cp.async.ca.shared.global [%0], [%1], 16;"
                 :: "r"(dst), "l"(src));
}

#define TILE_MAT 10240          // 128 rows * SLD * 2B
#define STAGE_B  (2 * TILE_MAT) // 20480 B (A + B)
#define OFF_A 0
#define OFF_B TILE_MAT

__global__ void __launch_bounds__(128, 2)
gemm_mma()
{
    extern __shared__ __align__(16) char smem[];
    uint32_t sb;
    asm("{ .reg .u64 t; cvta.to.shared.u64 t, %1; cvt.u32.u64 %0, t; }"
        : "=r"(sb) : "l"(smem));

    const int tid = threadIdx.x;
    const int wid = tid >> 5;          // 0..3
    const int lane = tid & 31;
    const int g = lane >> 2;
    const int t = lane & 3;
    const int m0 = blockIdx.y * 128;
    const int n0 = blockIdx.x * 128;
    const int wm = (wid & 1) * 64;     // warp row base
    const int wn = (wid >> 1) * 64;    // warp col base

    float acc[4][8][4];
#pragma unroll
    for (int i = 0; i < 4; i++)
#pragma unroll
        for (int j = 0; j < 8; j++)
#pragma unroll
            for (int q = 0; q < 4; q++) acc[i][j][q] = 0.f;

    auto stage_load = [&](int s, int kt) {
        uint32_t st = sb + s * STAGE_B;
#pragma unroll
        for (int i = 0; i < 4; i++) {
            int idx = tid + i * 128;
            int r = idx >> 2, q = idx & 3;
            size_t ga = (size_t)(m0 + r) * 256 + kt * 32 + q * 8;
            size_t gb = (size_t)(n0 + r) * 256 + kt * 32 + q * 8;
            uint32_t so = (uint32_t)(r * SLD + q * 8) * 2;
            cpa16(st + OFF_A + so, g_Af + ga);
            cpa16(st + OFF_B + so, g_Bf + gb);
        }
        asm volatile("cp.async.commit_group;" ::: "memory");
    };

    stage_load(0, 0);

    for (int kt = 0; kt < 8; kt++) {
        if (kt < 7) {
            stage_load((kt + 1) & 1, kt + 1);
            asm volatile("cp.async.wait_group 1;" ::: "memory");
        } else {
            asm volatile("cp.async.wait_group 0;" ::: "memory");
        }
        __syncthreads();

        uint32_t st = sb + (kt & 1) * STAGE_B;
        uint32_t bA = st + OFF_A, bB = st + OFF_B;

#pragma unroll
        for (int kk = 0; kk < 32; kk += 16) {
            uint32_t ah[4][4];
            int arow = (lane & 15);
            int akch = kk + ((lane >> 4) << 3);
#pragma unroll
            for (int mi = 0; mi < 4; mi++) {
                uint32_t ao = (uint32_t)((wm + mi * 16 + arow) * SLD + akch) * 2;
                ldsm4(ah[mi], bA + ao);
            }
            int brow = (lane & 7) + ((lane >> 4) << 3);
            int bkch = kk + (((lane >> 3) & 1) << 3);
#pragma unroll
            for (int npi = 0; npi < 4; npi++) {
                uint32_t bo =
                    (uint32_t)((wn + npi * 16 + brow) * SLD + bkch) * 2;
                uint32_t bb[4];
                ldsm4(bb, bB + bo);
                int n0i = npi * 2, n1i = npi * 2 + 1;
#pragma unroll
                for (int mi = 0; mi < 4; mi++) {
                    mma16816(acc[mi][n0i], ah[mi], bb[0], bb[1]);
                    mma16816(acc[mi][n1i], ah[mi], bb[2], bb[3]);
                }
            }
        }
        __syncthreads();
    }

    // epilogue: convert fp32 acc -> fp16 storage
#pragma unroll
    for (int mi = 0; mi < 4; mi++) {
        int row = m0 + wm + 16 * mi + g;
#pragma unroll
        for (int ni = 0; ni < 8; ni++) {
            int nc = n0 + wn + ni * 8 + t * 2;
            __half* baseh = (nc < 256) ? g_xlh : g_xrh;
            int col = nc & 255;
            *(__half2*)&baseh[(size_t)row * 256 + col] =
                __floats2half2_rn(acc[mi][ni][0], acc[mi][ni][1]);
            *(__half2*)&baseh[(size_t)(row + 8) * 256 + col] =
                __floats2half2_rn(acc[mi][ni][2], acc[mi][ni][3]);
        }
    }
}

// ============================================================
// CSR construction  (edge_index int32: row 0 = src, row 1 = dst)
// ============================================================
__global__ void zero_cnt_k(int M)
{
    int i = blockIdx.x * blockDim.x + threadIdx.x;
    if (i < M) g_cnt[i] = 0;
}

__global__ void count_k(const int* __restrict__ ei, int E)
{
    int e = blockIdx.x * blockDim.x + threadIdx.x;
    if (e < E) atomicAdd(&g_cnt[ei[E + e]], 1);
}

__global__ void scan1_k(int M)
{
    __shared__ int s[1024];
    int gi = blockIdx.x * 1024 + threadIdx.x;
    int v = (gi < M) ? g_cnt[gi] : 0;
    s[threadIdx.x] = v;
    __syncthreads();
#pragma unroll
    for (int off = 1; off < 1024; off <<= 1) {
        int tv = (threadIdx.x >= off) ? s[threadIdx.x - off] : 0;
        __syncthreads();
        s[threadIdx.x] += tv;
        __syncthreads();
    }
    if (gi < M) g_incl[gi] = s[threadIdx.x];
    if (threadIdx.x == 1023) g_bsum[blockIdx.x] = s[1023];
}

__global__ void scan2_k(int nb)
{
    if (threadIdx.x == 0 && blockIdx.x == 0) {
        int run = 0;
        for (int b = 0; b < nb; b++) { int tv = g_bsum[b]; g_bsum[b] = run; run += tv; }
    }
}

__global__ void scan3_k(int M)
{
    int i = blockIdx.x * blockDim.x + threadIdx.x;
    if (i < M) {
        int incl = g_incl[i] + g_bsum[i >> 10];
        g_incl[i] = incl;
        g_cursor[i] = incl - g_cnt[i];
    }
}

__global__ void scatter_k(const int* __restrict__ ei, int E)
{
    int e = blockIdx.x * blockDim.x + threadIdx.x;
    if (e < E) {
        int d = ei[E + e];
        int pos = atomicAdd(&g_cursor[d], 1);
        g_srcs[pos] = ei[e];
    }
}

// ============================================================
// GATv2 attention + aggregation, one warp per dst node.
// Lane l owns channels 8l..8l+7 (head l>>3); xl/xr rows are fp16,
// ONE uint4 load per lane per edge (512B/row gather).
// ============================================================
__device__ __forceinline__ void h8_to_f8(uint4 r, float4& A, float4& B)
{
    __half2* h = (__half2*)&r;
    float2 f0 = __half22float2(h[0]);
    float2 f1 = __half22float2(h[1]);
    float2 f2 = __half22float2(h[2]);
    float2 f3 = __half22float2(h[3]);
    A = make_float4(f0.x, f0.y, f1.x, f1.y);
    B = make_float4(f2.x, f2.y, f3.x, f3.y);
}

__device__ __forceinline__ float leaky4dot(float4 xl, float4 xr, float4 at)
{
    float z0 = xl.x + xr.x, z1 = xl.y + xr.y, z2 = xl.z + xr.z, z3 = xl.w + xr.w;
    float l0 = z0 > 0.f ? z0 : NEG_SLOPE * z0;
    float l1 = z1 > 0.f ? z1 : NEG_SLOPE * z1;
    float l2 = z2 > 0.f ? z2 : NEG_SLOPE * z2;
    float l3 = z3 > 0.f ? z3 : NEG_SLOPE * z3;
    return at.x * l0 + at.y * l1 + at.z * l2 + at.w * l3;
}

__device__ __forceinline__ float red8(float v)
{
    v += __shfl_xor_sync(0xffffffffu, v, 1);
    v += __shfl_xor_sync(0xffffffffu, v, 2);
    v += __shfl_xor_sync(0xffffffffu, v, 4);
    return v;
}

__global__ void __launch_bounds__(256)
agg_k(const float* __restrict__ att, const float* __restrict__ bias,
      float* __restrict__ out, int M)
{
    const int gwarp = (blockIdx.x * blockDim.x + threadIdx.x) >> 5;
    const int lane = threadIdx.x & 31;
    if (gwarp >= M) return;
    const int i = gwarp;
    const int c0 = lane * 8;

    float4 atA = *(const float4*)&att[c0];
    float4 atB = *(const float4*)&att[c0 + 4];
    float4 xrA, xrB;
    h8_to_f8(*(const uint4*)(g_xrh + (size_t)i * D_IN + c0), xrA, xrB);

    float m, d;
    float4 accA, accB;

    // ---- self loop (weight exp(0)=1) ----
    {
        float4 xlA, xlB;
        h8_to_f8(*(const uint4*)(g_xlh + (size_t)i * D_IN + c0), xlA, xlB);
        m = red8(leaky4dot(xlA, xrA, atA) + leaky4dot(xlB, xrB, atB));
        d = 1.f;
        accA = xlA; accB = xlB;
    }

    const int end = g_incl[i];
    int j = end - g_cnt[i];

    if (j < end) {
        int src = g_srcs[j];
        uint4 nraw = *(const uint4*)(g_xlh + (size_t)src * D_IN + c0);
        for (; j < end; j++) {
            uint4 raw = nraw;
            if (j + 1 < end) {
                int s2 = g_srcs[j + 1];
                nraw = *(const uint4*)(g_xlh + (size_t)s2 * D_IN + c0);
            }
            float4 xlA, xlB;
            h8_to_f8(raw, xlA, xlB);
            float p = red8(leaky4dot(xlA, xrA, atA) + leaky4dot(xlB, xrB, atB));

            float mn = fmaxf(m, p);
            float cw = __expf(m - mn), ww = __expf(p - mn);
            d = d * cw + ww; m = mn;
            accA.x = accA.x * cw + ww * xlA.x;
            accA.y = accA.y * cw + ww * xlA.y;
            accA.z = accA.z * cw + ww * xlA.z;
            accA.w = accA.w * cw + ww * xlA.w;
            accB.x = accB.x * cw + ww * xlB.x;
            accB.y = accB.y * cw + ww * xlB.y;
            accB.z = accB.z * cw + ww * xlB.z;
            accB.w = accB.w * cw + ww * xlB.w;
        }
    }

    float inv = 1.f / (d + 1e-16f);
    float z[8] = { accA.x * inv, accA.y * inv, accA.z * inv, accA.w * inv,
                   accB.x * inv, accB.y * inv, accB.z * inv, accB.w * inv };
    // mean over heads: lanes l, l^8, l^16, l^24 hold the same per-head channel
#pragma unroll
    for (int q = 0; q < 8; q++) {
        z[q] += __shfl_xor_sync(0xffffffffu, z[q], 8);
        z[q] += __shfl_xor_sync(0xffffffffu, z[q], 16);
    }

    if (lane < 8) {
#pragma unroll
        for (int q = 0; q < 8; q++) {
            float o = 0.25f * z[q] + bias[c0 + q];
            z[q] = o > 0.f ? o : expm1f(o);
        }
        float* dst = out + (size_t)i * D_OUT + c0;
        *(float4*)dst = make_float4(z[0], z[1], z[2], z[3]);
        *(float4*)(dst + 4) = make_float4(z[4], z[5], z[6], z[7]);
    }
}

// ============================================================
extern "C" void kernel_launch(void* const* d_in, const int* in_sizes, int n_in,
                              void* d_out, int out_size)
{
    const int* ei        = (const int*)d_in[1];
    const float* emb     = (const float*)d_in[2];
    const float* Wl      = (const float*)d_in[3];
    const float* Wr      = (const float*)d_in[4];
    const float* att     = (const float*)d_in[5];
    const float* bias    = (const float*)d_in[6];
    float* out           = (float*)d_out;

    const int E = in_sizes[1] / 2;         // 1,600,000
    const int M = in_sizes[2] / D_IN;      // 100,000
    const int T = (M + 127) / 128;         // 782 row tiles
    const int MP = T * 128;

    const int GEMM_SMEM = 2 * STAGE_B;     // 40960 B
    static int smem_set = 0;
    if (!smem_set) {
        cudaFuncSetAttribute(gemm_mma, cudaFuncAttributeMaxDynamicSharedMemorySize,
                             GEMM_SMEM);
        smem_set = 1;
    }

    int tb = 256;
    int n4 = M * 64, np4 = MP * 64;
    int nb = (M + 1023) / 1024;

    // single stream; gemm_mma kept in profile slot 4
    prepA_k<<<(np4 + 255) / 256, 256>>>((const float4*)emb, n4, np4);   // 1
    prepW_k<<<512, 256>>>(Wl, Wr);                                      // 2
    zero_cnt_k<<<(M + tb - 1) / tb, tb>>>(M);                           // 3
    gemm_mma<<<dim3(4, T), 128, GEMM_SMEM>>>();                         // 4
    count_k<<<(E + tb - 1) / tb, tb>>>(ei, E);                          // 5
    scan1_k<<<nb, 1024>>>(M);                                           // 6
    scan2_k<<<1, 32>>>(nb);                                             // 7
    scan3_k<<<(M + tb - 1) / tb, tb>>>(M);                              // 8
    scatter_k<<<(E + tb - 1) / tb, tb>>>(ei, E);                        // 9
    agg_k<<<(M + 7) / 8, 256>>>(att, bias, out, M);                     // 10

    (void)n_in; (void)out_size;
}

// round 14
// speedup vs baseline: 1.4416x; 1.0148x over previous
#include <cuda_runtime.h>
#include <cuda_fp16.h>
#include <cstdint>

#define N_NODE   100000
#define NODE_PAD 100096
#define D_IN     256
#define D_OUT    64
#define E_MAX    1600000
#define NEG_SLOPE 0.2f
#define SLD 40   // smem row stride in fp16 elems (80B)

// ---- scratch (__device__ globals; no allocation at runtime) ----
__device__ __half g_xlh[NODE_PAD * D_IN];   // emb @ W_l, fp16
__device__ __half g_xrh[NODE_PAD * D_IN];   // emb @ W_r, fp16
__device__ __half g_Af[NODE_PAD * D_IN];    // emb, fp16
__device__ __half g_Bf[512 * 256];          // rows 0-255: Wl^T, 256-511: Wr^T ([n][k])
__device__ int   g_cnt[N_NODE];
__device__ int   g_incl[N_NODE];
__device__ int   g_cursor[N_NODE];
__device__ int   g_srcs[E_MAX];
__device__ int   g_bsum[256];

// ============================================================
// Prep: fp32 -> fp16
// ============================================================
__global__ void prepA_k(const float4* __restrict__ emb4, int n4, int np4)
{
    int i = blockIdx.x * blockDim.x + threadIdx.x;
    if (i >= np4) return;
    float4 v = (i < n4) ? emb4[i] : make_float4(0.f, 0.f, 0.f, 0.f);
    __half2* hp = (__half2*)g_Af;
    hp[2 * i]     = __floats2half2_rn(v.x, v.y);
    hp[2 * i + 1] = __floats2half2_rn(v.z, v.w);
}

__global__ void prepW_k(const float* __restrict__ Wl, const float* __restrict__ Wr)
{
    int idx = blockIdx.x * blockDim.x + threadIdx.x;   // 512*256
    if (idx >= 512 * 256) return;
    int n = idx >> 8, k = idx & 255;
    float v = (n < 256) ? Wl[k * 256 + n] : Wr[k * 256 + (n - 256)];
    g_Bf[idx] = __float2half_rn(v);
}

// ============================================================
// mma.sync fp16 GEMM, cp.async double-buffered, ldmatrix frags.
// C[NODE_PAD,512] = A x [Wl|Wr]^T (single fp16, fp32 accum)
// CTA 128m x 128n, 8 warps of 64x32 (2m x 4n), 2 CTAs/SM
// -> 16 warps/SM for latency hiding (smem crossbar has headroom).
// ============================================================
__device__ __forceinline__ void mma16816(float c[4], const uint32_t a[4],
                                         const uint32_t b0, const uint32_t b1)
{
    asm volatile(
        "mma.sync.aligned.m16n8k16.row.col.f32.f16.f16.f32 "
        "{%0,%1,%2,%3}, {%4,%5,%6,%7}, {%8,%9}, {%0,%1,%2,%3};"
        : "+f"(c[0]), "+f"(c[1]), "+f"(c[2]), "+f"(c[3])
        : "r"(a[0]), "r"(a[1]), "r"(a[2]), "r"(a[3]), "r"(b0), "r"(b1));
}

__device__ __forceinline__ void ldsm4(uint32_t r[4], uint32_t addr)
{
    asm volatile("ldmatrix.sync.aligned.m8n8.x4.shared.b16 {%0,%1,%2,%3}, [%4];"
                 : "=r"(r[0]), "=r"(r[1]), "=r"(r[2]), "=r"(r[3]) : "r"(addr));
}

__device__ __forceinline__ void cpa16(uint32_t dst, const void* src)
{
    asm volatile("cp.async.ca.shared.global [%0], [%1], 16;"
                 :: "r"(dst), "l"(src));
}

#define TILE_MAT 10240          // 128 rows * SLD * 2B
#define STAGE_B  (2 * TILE_MAT) // 20480 B (A + B)
#define OFF_A 0
#define OFF_B TILE_MAT

__global__ void __launch_bounds__(256, 2)
gemm_mma()
{
    extern __shared__ __align__(16) char smem[];
    uint32_t sb;
    asm("{ .reg .u64 t; cvta.to.shared.u64 t, %1; cvt.u32.u64 %0, t; }"
        : "=r"(sb) : "l"(smem));

    const int tid = threadIdx.x;
    const int wid = tid >> 5;          // 0..7
    const int lane = tid & 31;
    const int g = lane >> 2;
    const int t = lane & 3;
    const int m0 = blockIdx.y * 128;
    const int n0 = blockIdx.x * 128;
    const int wm = (wid & 1) * 64;     // warp row base (0/64)
    const int wn = (wid >> 1) * 32;    // warp col base (0/32/64/96)

    float acc[4][4][4];
#pragma unroll
    for (int i = 0; i < 4; i++)
#pragma unroll
        for (int j = 0; j < 4; j++)
#pragma unroll
            for (int q = 0; q < 4; q++) acc[i][j][q] = 0.f;

    auto stage_load = [&](int s, int kt) {
        uint32_t st = sb + s * STAGE_B;
#pragma unroll
        for (int i = 0; i < 2; i++) {
            int idx = tid + i * 256;
            int r = idx >> 2, q = idx & 3;
            size_t ga = (size_t)(m0 + r) * 256 + kt * 32 + q * 8;
            size_t gb = (size_t)(n0 + r) * 256 + kt * 32 + q * 8;
            uint32_t so = (uint32_t)(r * SLD + q * 8) * 2;
            cpa16(st + OFF_A + so, g_Af + ga);
            cpa16(st + OFF_B + so, g_Bf + gb);
        }
        asm volatile("cp.async.commit_group;" ::: "memory");
    };

    stage_load(0, 0);

    for (int kt = 0; kt < 8; kt++) {
        if (kt < 7) {
            stage_load((kt + 1) & 1, kt + 1);
            asm volatile("cp.async.wait_group 1;" ::: "memory");
        } else {
            asm volatile("cp.async.wait_group 0;" ::: "memory");
        }
        __syncthreads();

        uint32_t st = sb + (kt & 1) * STAGE_B;
        uint32_t bA = st + OFF_A, bB = st + OFF_B;

#pragma unroll
        for (int kk = 0; kk < 32; kk += 16) {
            uint32_t ah[4][4];
            int arow = (lane & 15);
            int akch = kk + ((lane >> 4) << 3);
#pragma unroll
            for (int mi = 0; mi < 4; mi++) {
                uint32_t ao = (uint32_t)((wm + mi * 16 + arow) * SLD + akch) * 2;
                ldsm4(ah[mi], bA + ao);
            }
            int brow = (lane & 7) + ((lane >> 4) << 3);
            int bkch = kk + (((lane >> 3) & 1) << 3);
#pragma unroll
            for (int npi = 0; npi < 2; npi++) {
                uint32_t bo =
                    (uint32_t)((wn + npi * 16 + brow) * SLD + bkch) * 2;
                uint32_t bb[4];
                ldsm4(bb, bB + bo);
                int n0i = npi * 2, n1i = npi * 2 + 1;
#pragma unroll
                for (int mi = 0; mi < 4; mi++) {
                    mma16816(acc[mi][n0i], ah[mi], bb[0], bb[1]);
                    mma16816(acc[mi][n1i], ah[mi], bb[2], bb[3]);
                }
            }
        }
        __syncthreads();
    }

    // epilogue: convert fp32 acc -> fp16 storage
#pragma unroll
    for (int mi = 0; mi < 4; mi++) {
        int row = m0 + wm + 16 * mi + g;
#pragma unroll
        for (int ni = 0; ni < 4; ni++) {
            int nc = n0 + wn + ni * 8 + t * 2;
            __half* baseh = (nc < 256) ? g_xlh : g_xrh;
            int col = nc & 255;
            *(__half2*)&baseh[(size_t)row * 256 + col] =
                __floats2half2_rn(acc[mi][ni][0], acc[mi][ni][1]);
            *(__half2*)&baseh[(size_t)(row + 8) * 256 + col] =
                __floats2half2_rn(acc[mi][ni][2], acc[mi][ni][3]);
        }
    }
}

// ============================================================
// CSR construction  (edge_index int32: row 0 = src, row 1 = dst)
// ============================================================
__global__ void zero_cnt_k(int M)
{
    int i = blockIdx.x * blockDim.x + threadIdx.x;
    if (i < M) g_cnt[i] = 0;
}

__global__ void count_k(const int* __restrict__ ei, int E)
{
    int e = blockIdx.x * blockDim.x + threadIdx.x;
    if (e < E) atomicAdd(&g_cnt[ei[E + e]], 1);
}

__global__ void scan1_k(int M)
{
    __shared__ int s[1024];
    int gi = blockIdx.x * 1024 + threadIdx.x;
    int v = (gi < M) ? g_cnt[gi] : 0;
    s[threadIdx.x] = v;
    __syncthreads();
#pragma unroll
    for (int off = 1; off < 1024; off <<= 1) {
        int tv = (threadIdx.x >= off) ? s[threadIdx.x - off] : 0;
        __syncthreads();
        s[threadIdx.x] += tv;
        __syncthreads();
    }
    if (gi < M) g_incl[gi] = s[threadIdx.x];
    if (threadIdx.x == 1023) g_bsum[blockIdx.x] = s[1023];
}

__global__ void scan2_k(int nb)
{
    if (threadIdx.x == 0 && blockIdx.x == 0) {
        int run = 0;
        for (int b = 0; b < nb; b++) { int tv = g_bsum[b]; g_bsum[b] = run; run += tv; }
    }
}

__global__ void scan3_k(int M)
{
    int i = blockIdx.x * blockDim.x + threadIdx.x;
    if (i < M) {
        int incl = g_incl[i] + g_bsum[i >> 10];
        g_incl[i] = incl;
        g_cursor[i] = incl - g_cnt[i];
    }
}

__global__ void scatter_k(const int* __restrict__ ei, int E)
{
    int e = blockIdx.x * blockDim.x + threadIdx.x;
    if (e < E) {
        int d = ei[E + e];
        int pos = atomicAdd(&g_cursor[d], 1);
        g_srcs[pos] = ei[e];
    }
}

// ============================================================
// GATv2 attention + aggregation, one warp per dst node.
// Lane l owns channels 8l..8l+7 (head l>>3), fp16 rows,
// one uint4/lane/edge. Edge pairs: interleaved 3-SHFL reductions
// halve the dependent-shuffle critical path; single softmax state.
// ============================================================
__device__ __forceinline__ void h8_to_f8(uint4 r, float4& A, float4& B)
{
    __half2* h = (__half2*)&r;
    float2 f0 = __half22float2(h[0]);
    float2 f1 = __half22float2(h[1]);
    float2 f2 = __half22float2(h[2]);
    float2 f3 = __half22float2(h[3]);
    A = make_float4(f0.x, f0.y, f1.x, f1.y);
    B = make_float4(f2.x, f2.y, f3.x, f3.y);
}

__device__ __forceinline__ float leaky4dot(float4 xl, float4 xr, float4 at)
{
    float z0 = xl.x + xr.x, z1 = xl.y + xr.y, z2 = xl.z + xr.z, z3 = xl.w + xr.w;
    float l0 = z0 > 0.f ? z0 : NEG_SLOPE * z0;
    float l1 = z1 > 0.f ? z1 : NEG_SLOPE * z1;
    float l2 = z2 > 0.f ? z2 : NEG_SLOPE * z2;
    float l3 = z3 > 0.f ? z3 : NEG_SLOPE * z3;
    return at.x * l0 + at.y * l1 + at.z * l2 + at.w * l3;
}

__device__ __forceinline__ float red8(float v)
{
    v += __shfl_xor_sync(0xffffffffu, v, 1);
    v += __shfl_xor_sync(0xffffffffu, v, 2);
    v += __shfl_xor_sync(0xffffffffu, v, 4);
    return v;
}

__global__ void __launch_bounds__(256)
agg_k(const float* __restrict__ att, const float* __restrict__ bias,
      float* __restrict__ out, int M)
{
    const int gwarp = (blockIdx.x * blockDim.x + threadIdx.x) >> 5;
    const int lane = threadIdx.x & 31;
    if (gwarp >= M) return;
    const int i = gwarp;
    const int c0 = lane * 8;

    float4 atA = *(const float4*)&att[c0];
    float4 atB = *(const float4*)&att[c0 + 4];
    float4 xrA, xrB;
    h8_to_f8(*(const uint4*)(g_xrh + (size_t)i * D_IN + c0), xrA, xrB);

    float m, d;
    float4 accA, accB;

    // ---- self loop (weight exp(0)=1) ----
    {
        float4 xlA, xlB;
        h8_to_f8(*(const uint4*)(g_xlh + (size_t)i * D_IN + c0), xlA, xlB);
        m = red8(leaky4dot(xlA, xrA, atA) + leaky4dot(xlB, xrB, atB));
        d = 1.f;
        accA = xlA; accB = xlB;
    }

    const int end = g_incl[i];
    int j = end - g_cnt[i];
    const int cnt = end - j;

    // peel one edge if count is odd
    if (cnt & 1) {
        int src = g_srcs[j];
        float4 xlA, xlB;
        h8_to_f8(*(const uint4*)(g_xlh + (size_t)src * D_IN + c0), xlA, xlB);
        float p = red8(leaky4dot(xlA, xrA, atA) + leaky4dot(xlB, xrB, atB));
        float mn = fmaxf(m, p);
        float cw = __expf(m - mn), ww = __expf(p - mn);
        d = d * cw + ww; m = mn;
        accA.x = accA.x * cw + ww * xlA.x;
        accA.y = accA.y * cw + ww * xlA.y;
        accA.z = accA.z * cw + ww * xlA.z;
        accA.w = accA.w * cw + ww * xlA.w;
        accB.x = accB.x * cw + ww * xlB.x;
        accB.y = accB.y * cw + ww * xlB.y;
        accB.z = accB.z * cw + ww * xlB.z;
        accB.w = accB.w * cw + ww * xlB.w;
        j++;
    }

    // pairs: interleaved loads + interleaved reductions, sequential updates
    for (; j < end; j += 2) {
        int s0 = g_srcs[j];
        int s1 = g_srcs[j + 1];
        uint4 r0 = *(const uint4*)(g_xlh + (size_t)s0 * D_IN + c0);
        uint4 r1 = *(const uint4*)(g_xlh + (size_t)s1 * D_IN + c0);
        float4 aA, aB, bA, bB;
        h8_to_f8(r0, aA, aB);
        h8_to_f8(r1, bA, bB);
        float p0 = leaky4dot(aA, xrA, atA) + leaky4dot(aB, xrB, atB);
        float p1 = leaky4dot(bA, xrA, atA) + leaky4dot(bB, xrB, atB);
        p0 += __shfl_xor_sync(0xffffffffu, p0, 1);
        p1 += __shfl_xor_sync(0xffffffffu, p1, 1);
        p0 += __shfl_xor_sync(0xffffffffu, p0, 2);
        p1 += __shfl_xor_sync(0xffffffffu, p1, 2);
        p0 += __shfl_xor_sync(0xffffffffu, p0, 4);
        p1 += __shfl_xor_sync(0xffffffffu, p1, 4);

        {
            float mn = fmaxf(m, p0);
            float cw = __expf(m - mn), ww = __expf(p0 - mn);
            d = d * cw + ww; m = mn;
            accA.x = accA.x * cw + ww * aA.x;
            accA.y = accA.y * cw + ww * aA.y;
            accA.z = accA.z * cw + ww * aA.z;
            accA.w = accA.w * cw + ww * aA.w;
            accB.x = accB.x * cw + ww * aB.x;
            accB.y = accB.y * cw + ww * aB.y;
            accB.z = accB.z * cw + ww * aB.z;
            accB.w = accB.w * cw + ww * aB.w;
        }
        {
            float mn = fmaxf(m, p1);
            float cw = __expf(m - mn), ww = __expf(p1 - mn);
            d = d * cw + ww; m = mn;
            accA.x = accA.x * cw + ww * bA.x;
            accA.y = accA.y * cw + ww * bA.y;
            accA.z = accA.z * cw + ww * bA.z;
            accA.w = accA.w * cw + ww * bA.w;
            accB.x = accB.x * cw + ww * bB.x;
            accB.y = accB.y * cw + ww * bB.y;
            accB.z = accB.z * cw + ww * bB.z;
            accB.w = accB.w * cw + ww * bB.w;
        }
    }

    float inv = 1.f / (d + 1e-16f);
    float z[8] = { accA.x * inv, accA.y * inv, accA.z * inv, accA.w * inv,
                   accB.x * inv, accB.y * inv, accB.z * inv, accB.w * inv };
    // mean over heads: lanes l, l^8, l^16, l^24 hold the same per-head channel
#pragma unroll
    for (int q = 0; q < 8; q++) {
        z[q] += __shfl_xor_sync(0xffffffffu, z[q], 8);
        z[q] += __shfl_xor_sync(0xffffffffu, z[q], 16);
    }

    if (lane < 8) {
#pragma unroll
        for (int q = 0; q < 8; q++) {
            float o = 0.25f * z[q] + bias[c0 + q];
            z[q] = o > 0.f ? o : expm1f(o);
        }
        float* dst = out + (size_t)i * D_OUT + c0;
        *(float4*)dst = make_float4(z[0], z[1], z[2], z[3]);
        *(float4*)(dst + 4) = make_float4(z[4], z[5], z[6], z[7]);
    }
}

// ============================================================
extern "C" void kernel_launch(void* const* d_in, const int* in_sizes, int n_in,
                              void* d_out, int out_size)
{
    const int* ei        = (const int*)d_in[1];
    const float* emb     = (const float*)d_in[2];
    const float* Wl      = (const float*)d_in[3];
    const float* Wr      = (const float*)d_in[4];
    const float* att     = (const float*)d_in[5];
    const float* bias    = (const float*)d_in[6];
    float* out           = (float*)d_out;

    const int E = in_sizes[1] / 2;         // 1,600,000
    const int M = in_sizes[2] / D_IN;      // 100,000
    const int T = (M + 127) / 128;         // 782 row tiles
    const int MP = T * 128;

    const int GEMM_SMEM = 2 * STAGE_B;     // 40960 B
    static int smem_set = 0;
    if (!smem_set) {
        cudaFuncSetAttribute(gemm_mma, cudaFuncAttributeMaxDynamicSharedMemorySize,
                             GEMM_SMEM);
        smem_set = 1;
    }

    int tb = 256;
    int n4 = M * 64, np4 = MP * 64;
    int nb = (M + 1023) / 1024;

    // single stream; gemm_mma kept in profile slot 4
    prepA_k<<<(np4 + 255) / 256, 256>>>((const float4*)emb, n4, np4);   // 1
    prepW_k<<<512, 256>>>(Wl, Wr);                                      // 2
    zero_cnt_k<<<(M + tb - 1) / tb, tb>>>(M);                           // 3
    gemm_mma<<<dim3(4, T), 256, GEMM_SMEM>>>();                         // 4
    count_k<<<(E + tb - 1) / tb, tb>>>(ei, E);                          // 5
    scan1_k<<<nb, 1024>>>(M);                                           // 6
    scan2_k<<<1, 32>>>(nb);                                             // 7
    scan3_k<<<(M + tb - 1) / tb, tb>>>(M);                              // 8
    scatter_k<<<(E + tb - 1) / tb, tb>>>(ei, E);                        // 9
    agg_k<<<(M + 7) / 8, 256>>>(att, bias, out, M);                     // 10

    (void)n_in; (void)out_size;
}

// round 15
// speedup vs baseline: 1.6572x; 1.1496x over previous
#include <cuda_runtime.h>
#include <cuda_fp16.h>
#include <cstdint>

#define N_NODE   100000
#define NODE_PAD 100096
#define D_IN     256
#define D_OUT    64
#define E_MAX    1600000
#define NEG_SLOPE 0.2f
#define SLD 40   // smem row stride in fp16 elems (80B)

// ---- scratch (__device__ globals; no allocation at runtime) ----
__device__ __half g_xlh[NODE_PAD * D_IN];   // emb @ W_l, fp16
__device__ __half g_xrh[NODE_PAD * D_IN];   // emb @ W_r, fp16
__device__ __half g_Af[NODE_PAD * D_IN];    // emb, fp16
__device__ __half g_Bf[512 * 256];          // rows 0-255: Wl^T, 256-511: Wr^T ([n][k])
__device__ int   g_cnt[N_NODE];
__device__ int   g_incl[N_NODE];
__device__ int   g_cursor[N_NODE];
__device__ int   g_srcs[E_MAX];
__device__ int   g_bsum[256];

// ============================================================
// Prep: fp32 -> fp16
// ============================================================
__global__ void prepA_k(const float4* __restrict__ emb4, int n4, int np4)
{
    int i = blockIdx.x * blockDim.x + threadIdx.x;
    if (i >= np4) return;
    float4 v = (i < n4) ? emb4[i] : make_float4(0.f, 0.f, 0.f, 0.f);
    __half2* hp = (__half2*)g_Af;
    hp[2 * i]     = __floats2half2_rn(v.x, v.y);
    hp[2 * i + 1] = __floats2half2_rn(v.z, v.w);
}

__global__ void prepW_k(const float* __restrict__ Wl, const float* __restrict__ Wr)
{
    int idx = blockIdx.x * blockDim.x + threadIdx.x;   // 512*256
    if (idx >= 512 * 256) return;
    int n = idx >> 8, k = idx & 255;
    float v = (n < 256) ? Wl[k * 256 + n] : Wr[k * 256 + (n - 256)];
    g_Bf[idx] = __float2half_rn(v);
}

// ============================================================
// mma.sync fp16 GEMM, cp.async double-buffered, ldmatrix frags.
// C[NODE_PAD,512] = A x [Wl|Wr]^T (single fp16, fp32 accum)
// CTA 128m x 128n, 4 warps of 64x64 (2x2), 2 CTAs/SM.  (R13 config)
// ============================================================
__device__ __forceinline__ void mma16816(float c[4], const uint32_t a[4],
                                         const uint32_t b0, const uint32_t b1)
{
    asm volatile(
        "mma.sync.aligned.m16n8k16.row.col.f32.f16.f16.f32 "
        "{%0,%1,%2,%3}, {%4,%5,%6,%7}, {%8,%9}, {%0,%1,%2,%3};"
        : "+f"(c[0]), "+f"(c[1]), "+f"(c[2]), "+f"(c[3])
        : "r"(a[0]), "r"(a[1]), "r"(a[2]), "r"(a[3]), "r"(b0), "r"(b1));
}

__device__ __forceinline__ void ldsm4(uint32_t r[4], uint32_t addr)
{
    asm volatile("ldmatrix.sync.aligned.m8n8.x4.shared.b16 {%0,%1,%2,%3}, [%4];"
                 : "=r"(r[0]), "=r"(r[1]), "=r"(r[2]), "=r"(r[3]) : "r"(addr));
}

__device__ __forceinline__ void cpa16(uint32_t dst, const void* src)
{
    asm volatile("cp.async.ca.shared.global [%0], [%1], 16;"
                 :: "r"(dst), "l"(src));
}

#define TILE_MAT 10240          // 128 rows * SLD * 2B
#define STAGE_B  (2 * TILE_MAT) // 20480 B (A + B)
#define OFF_A 0
#define OFF_B TILE_MAT

__global__ void __launch_bounds__(128, 2)
gemm_mma()
{
    extern __shared__ __align__(16) char smem[];
    uint32_t sb;
    asm("{ .reg .u64 t; cvta.to.shared.u64 t, %1; cvt.u32.u64 %0, t; }"
        : "=r"(sb) : "l"(smem));

    const int tid = threadIdx.x;
    const int wid = tid >> 5;          // 0..3
    const int lane = tid & 31;
    const int g = lane >> 2;
    const int t = lane & 3;
    const int m0 = blockIdx.y * 128;
    const int n0 = blockIdx.x * 128;
    const int wm = (wid & 1) * 64;     // warp row base
    const int wn = (wid >> 1) * 64;    // warp col base

    float acc[4][8][4];
#pragma unroll
    for (int i = 0; i < 4; i++)
#pragma unroll
        for (int j = 0; j < 8; j++)
#pragma unroll
            for (int q = 0; q < 4; q++) acc[i][j][q] = 0.f;

    auto stage_load = [&](int s, int kt) {
        uint32_t st = sb + s * STAGE_B;
#pragma unroll
        for (int i = 0; i < 4; i++) {
            int idx = tid + i * 128;
            int r = idx >> 2, q = idx & 3;
            size_t ga = (size_t)(m0 + r) * 256 + kt * 32 + q * 8;
            size_t gb = (size_t)(n0 + r) * 256 + kt * 32 + q * 8;
            uint32_t so = (uint32_t)(r * SLD + q * 8) * 2;
            cpa16(st + OFF_A + so, g_Af + ga);
            cpa16(st + OFF_B + so, g_Bf + gb);
        }
        asm volatile("cp.async.commit_group;" ::: "memory");
    };

    stage_load(0, 0);

    for (int kt = 0; kt < 8; kt++) {
        if (kt < 7) {
            stage_load((kt + 1) & 1, kt + 1);
            asm volatile("cp.async.wait_group 1;" ::: "memory");
        } else {
            asm volatile("cp.async.wait_group 0;" ::: "memory");
        }
        __syncthreads();

        uint32_t st = sb + (kt & 1) * STAGE_B;
        uint32_t bA = st + OFF_A, bB = st + OFF_B;

#pragma unroll
        for (int kk = 0; kk < 32; kk += 16) {
            uint32_t ah[4][4];
            int arow = (lane & 15);
            int akch = kk + ((lane >> 4) << 3);
#pragma unroll
            for (int mi = 0; mi < 4; mi++) {
                uint32_t ao = (uint32_t)((wm + mi * 16 + arow) * SLD + akch) * 2;
                ldsm4(ah[mi], bA + ao);
            }
            int brow = (lane & 7) + ((lane >> 4) << 3);
            int bkch = kk + (((lane >> 3) & 1) << 3);
#pragma unroll
            for (int npi = 0; npi < 4; npi++) {
                uint32_t bo =
                    (uint32_t)((wn + npi * 16 + brow) * SLD + bkch) * 2;
                uint32_t bb[4];
                ldsm4(bb, bB + bo);
                int n0i = npi * 2, n1i = npi * 2 + 1;
#pragma unroll
                for (int mi = 0; mi < 4; mi++) {
                    mma16816(acc[mi][n0i], ah[mi], bb[0], bb[1]);
                    mma16816(acc[mi][n1i], ah[mi], bb[2], bb[3]);
                }
            }
        }
        __syncthreads();
    }

    // epilogue: convert fp32 acc -> fp16 storage
#pragma unroll
    for (int mi = 0; mi < 4; mi++) {
        int row = m0 + wm + 16 * mi + g;
#pragma unroll
        for (int ni = 0; ni < 8; ni++) {
            int nc = n0 + wn + ni * 8 + t * 2;
            __half* baseh = (nc < 256) ? g_xlh : g_xrh;
            int col = nc & 255;
            *(__half2*)&baseh[(size_t)row * 256 + col] =
                __floats2half2_rn(acc[mi][ni][0], acc[mi][ni][1]);
            *(__half2*)&baseh[(size_t)(row + 8) * 256 + col] =
                __floats2half2_rn(acc[mi][ni][2], acc[mi][ni][3]);
        }
    }
}

// ============================================================
// CSR construction  (edge_index int32: row 0 = src, row 1 = dst)
// ============================================================
__global__ void zero_cnt_k(int M)
{
    int i = blockIdx.x * blockDim.x + threadIdx.x;
    if (i < M) g_cnt[i] = 0;
}

__global__ void count_k(const int* __restrict__ ei, int E)
{
    int e = blockIdx.x * blockDim.x + threadIdx.x;
    if (e < E) atomicAdd(&g_cnt[ei[E + e]], 1);
}

__global__ void scan1_k(int M)
{
    __shared__ int s[1024];
    int gi = blockIdx.x * 1024 + threadIdx.x;
    int v = (gi < M) ? g_cnt[gi] : 0;
    s[threadIdx.x] = v;
    __syncthreads();
#pragma unroll
    for (int off = 1; off < 1024; off <<= 1) {
        int tv = (threadIdx.x >= off) ? s[threadIdx.x - off] : 0;
        __syncthreads();
        s[threadIdx.x] += tv;
        __syncthreads();
    }
    if (gi < M) g_incl[gi] = s[threadIdx.x];
    if (threadIdx.x == 1023) g_bsum[blockIdx.x] = s[1023];
}

__global__ void scan2_k(int nb)
{
    if (threadIdx.x == 0 && blockIdx.x == 0) {
        int run = 0;
        for (int b = 0; b < nb; b++) { int tv = g_bsum[b]; g_bsum[b] = run; run += tv; }
    }
}

__global__ void scan3_k(int M)
{
    int i = blockIdx.x * blockDim.x + threadIdx.x;
    if (i < M) {
        int incl = g_incl[i] + g_bsum[i >> 10];
        g_incl[i] = incl;
        g_cursor[i] = incl - g_cnt[i];
    }
}

__global__ void scatter_k(const int* __restrict__ ei, int E)
{
    int e = blockIdx.x * blockDim.x + threadIdx.x;
    if (e < E) {
        int d = ei[E + e];
        int pos = atomicAdd(&g_cursor[d], 1);
        g_srcs[pos] = ei[e];
    }
}

// ============================================================
// GATv2 attention + aggregation, one warp per dst node.
// Lane l owns channels 8l..8l+7 (head l>>3), fp16 rows.
// m=0 softmax (scores provably tiny), half2 score path.
// ============================================================
__device__ __forceinline__ float score_h2(uint4 xlr, const __half2 xr2[4],
                                          const __half2 at2[4], __half2 c02)
{
    const __half2* xl2 = (const __half2*)&xlr;
    __half2 p2;
#pragma unroll
    for (int k = 0; k < 4; k++) {
        __half2 z = __hadd2(xl2[k], xr2[k]);
        __half2 lz = __hmax2(z, __hmul2(z, c02));
        p2 = (k == 0) ? __hmul2(at2[0], lz) : __hfma2(at2[k], lz, p2);
    }
    float2 pf = __half22float2(p2);
    return pf.x + pf.y;
}

__device__ __forceinline__ void h8_to_f8(uint4 r, float4& A, float4& B)
{
    __half2* h = (__half2*)&r;
    float2 f0 = __half22float2(h[0]);
    float2 f1 = __half22float2(h[1]);
    float2 f2 = __half22float2(h[2]);
    float2 f3 = __half22float2(h[3]);
    A = make_float4(f0.x, f0.y, f1.x, f1.y);
    B = make_float4(f2.x, f2.y, f3.x, f3.y);
}

__global__ void __launch_bounds__(256)
agg_k(const float* __restrict__ att, const float* __restrict__ bias,
      float* __restrict__ out, int M)
{
    const int gwarp = (blockIdx.x * blockDim.x + threadIdx.x) >> 5;
    const int lane = threadIdx.x & 31;
    if (gwarp >= M) return;
    const int i = gwarp;
    const int c0 = lane * 8;
    const __half2 c02 = __float2half2_rn(NEG_SLOPE);

    // att -> half2 (once per node)
    __half2 at2[4];
#pragma unroll
    for (int k = 0; k < 4; k++) {
        float2 a = *(const float2*)&att[c0 + 2 * k];
        at2[k] = __floats2half2_rn(a.x, a.y);
    }
    uint4 xr_raw = *(const uint4*)(g_xrh + (size_t)i * D_IN + c0);
    __half2 xr2[4];
#pragma unroll
    for (int k = 0; k < 4; k++) xr2[k] = ((const __half2*)&xr_raw)[k];

    float d = 0.f;
    float4 accA = make_float4(0.f, 0.f, 0.f, 0.f);
    float4 accB = make_float4(0.f, 0.f, 0.f, 0.f);

    // single-item processor (self loop / odd peel)
    auto one = [&](uint4 raw) {
        float p = score_h2(raw, xr2, at2, c02);
        p += __shfl_xor_sync(0xffffffffu, p, 1);
        p += __shfl_xor_sync(0xffffffffu, p, 2);
        p += __shfl_xor_sync(0xffffffffu, p, 4);
        float w = __expf(fminf(p, 60.f));
        float4 xlA, xlB;
        h8_to_f8(raw, xlA, xlB);
        d += w;
        accA.x += w * xlA.x; accA.y += w * xlA.y;
        accA.z += w * xlA.z; accA.w += w * xlA.w;
        accB.x += w * xlB.x; accB.y += w * xlB.y;
        accB.z += w * xlB.z; accB.w += w * xlB.w;
    };

    // self loop
    one(*(const uint4*)(g_xlh + (size_t)i * D_IN + c0));

    const int end = g_incl[i];
    int j = end - g_cnt[i];
    const int cnt = end - j;

    if (cnt & 1) {
        int src = g_srcs[j];
        one(*(const uint4*)(g_xlh + (size_t)src * D_IN + c0));
        j++;
    }

    // pairs: interleaved loads, scores, reductions; independent updates
    for (; j < end; j += 2) {
        int s0 = g_srcs[j];
        int s1 = g_srcs[j + 1];
        uint4 r0 = *(const uint4*)(g_xlh + (size_t)s0 * D_IN + c0);
        uint4 r1 = *(const uint4*)(g_xlh + (size_t)s1 * D_IN + c0);
        float p0 = score_h2(r0, xr2, at2, c02);
        float p1 = score_h2(r1, xr2, at2, c02);
        p0 += __shfl_xor_sync(0xffffffffu, p0, 1);
        p1 += __shfl_xor_sync(0xffffffffu, p1, 1);
        p0 += __shfl_xor_sync(0xffffffffu, p0, 2);
        p1 += __shfl_xor_sync(0xffffffffu, p1, 2);
        p0 += __shfl_xor_sync(0xffffffffu, p0, 4);
        p1 += __shfl_xor_sync(0xffffffffu, p1, 4);
        float w0 = __expf(fminf(p0, 60.f));
        float w1 = __expf(fminf(p1, 60.f));
        float4 aA, aB, bA, bB;
        h8_to_f8(r0, aA, aB);
        h8_to_f8(r1, bA, bB);
        d += w0 + w1;
        accA.x += w0 * aA.x + w1 * bA.x;
        accA.y += w0 * aA.y + w1 * bA.y;
        accA.z += w0 * aA.z + w1 * bA.z;
        accA.w += w0 * aA.w + w1 * bA.w;
        accB.x += w0 * aB.x + w1 * bB.x;
        accB.y += w0 * aB.y + w1 * bB.y;
        accB.z += w0 * aB.z + w1 * bB.z;
        accB.w += w0 * aB.w + w1 * bB.w;
    }

    float inv = 1.f / (d + 1e-16f);
    float z[8] = { accA.x * inv, accA.y * inv, accA.z * inv, accA.w * inv,
                   accB.x * inv, accB.y * inv, accB.z * inv, accB.w * inv };
    // mean over heads: lanes l, l^8, l^16, l^24 hold the same per-head channel
#pragma unroll
    for (int q = 0; q < 8; q++) {
        z[q] += __shfl_xor_sync(0xffffffffu, z[q], 8);
        z[q] += __shfl_xor_sync(0xffffffffu, z[q], 16);
    }

    if (lane < 8) {
#pragma unroll
        for (int q = 0; q < 8; q++) {
            float o = 0.25f * z[q] + bias[c0 + q];
            z[q] = o > 0.f ? o : expm1f(o);
        }
        float* dst = out + (size_t)i * D_OUT + c0;
        *(float4*)dst = make_float4(z[0], z[1], z[2], z[3]);
        *(float4*)(dst + 4) = make_float4(z[4], z[5], z[6], z[7]);
    }
}

// ============================================================
extern "C" void kernel_launch(void* const* d_in, const int* in_sizes, int n_in,
                              void* d_out, int out_size)
{
    const int* ei        = (const int*)d_in[1];
    const float* emb     = (const float*)d_in[2];
    const float* Wl      = (const float*)d_in[3];
    const float* Wr      = (const float*)d_in[4];
    const float* att     = (const float*)d_in[5];
    const float* bias    = (const float*)d_in[6];
    float* out           = (float*)d_out;

    const int E = in_sizes[1] / 2;         // 1,600,000
    const int M = in_sizes[2] / D_IN;      // 100,000
    const int T = (M + 127) / 128;         // 782 row tiles
    const int MP = T * 128;

    const int GEMM_SMEM = 2 * STAGE_B;     // 40960 B
    static int smem_set = 0;
    if (!smem_set) {
        cudaFuncSetAttribute(gemm_mma, cudaFuncAttributeMaxDynamicSharedMemorySize,
                             GEMM_SMEM);
        smem_set = 1;
    }

    int tb = 256;
    int n4 = M * 64, np4 = MP * 64;
    int nb = (M + 1023) / 1024;

    // single stream; gemm_mma kept in profile slot 4
    prepA_k<<<(np4 + 255) / 256, 256>>>((const float4*)emb, n4, np4);   // 1
    prepW_k<<<512, 256>>>(Wl, Wr);                                      // 2
    zero_cnt_k<<<(M + tb - 1) / tb, tb>>>(M);                           // 3
    gemm_mma<<<dim3(4, T), 128, GEMM_SMEM>>>();                         // 4
    count_k<<<(E + tb - 1) / tb, tb>>>(ei, E);                          // 5
    scan1_k<<<nb, 1024>>>(M);                                           // 6
    scan2_k<<<1, 32>>>(nb);                                             // 7
    scan3_k<<<(M + tb - 1) / tb, tb>>>(M);                              // 8
    scatter_k<<<(E + tb - 1) / tb, tb>>>(ei, E);                        // 9
    agg_k<<<(M + 7) / 8, 256>>>(att, bias, out, M);                     // 10

    (void)n_in; (void)out_size;
}